// round 10
// baseline (speedup 1.0000x reference)
#include <cuda_runtime.h>
#include <cuda.h>
#include <math.h>
#include <stdint.h>

// ---------------------------------------------------------------------------
// Feature detection: tcgen05/TMA-tensor are arch-SPECIFIC (sm_103a / sm_100a).
// ---------------------------------------------------------------------------
#ifdef __CUDA_ARCH_HAS_FEATURE__
#define TC_FEAT_103 __CUDA_ARCH_HAS_FEATURE__(SM103_ALL)
#define TC_FEAT_100 __CUDA_ARCH_HAS_FEATURE__(SM100_ALL)
#else
#define TC_FEAT_103 0
#define TC_FEAT_100 0
#endif
#if defined(__CUDA_ARCH__) && (TC_FEAT_103 || TC_FEAT_100 || \
    defined(__CUDA_ARCH_FEAT_SM103_ALL) || defined(__CUDA_ARCH_FEAT_SM100_ALL))
#define TC_OK 1
#else
#define TC_OK 0
#endif

// ---------------------------------------------------------------------------
// Global scratch (static; no allocations allowed).
// ---------------------------------------------------------------------------
static __device__ float g_t_r [117440512ull]; // 8192*14336 (tf32-rounded t)
static __device__ float g_x_r [33554432ull];  // 8192*4096
static __device__ float g_wu_r[58720256ull];  // 14336*4096
static __device__ float g_wg_r[58720256ull];
static __device__ float g_wd_r[58720256ull];  // 4096*14336
static constexpr unsigned FIX_CAP = 8388608u;
static __device__ unsigned g_fix_cnt;
static __device__ unsigned g_fix_list[FIX_CAP];

// Flag word layout: bit27 = approx mask, bits[14..26] = token, bits[0..13] = neuron.
#define FIX_DELTA 1.5e-3f
static constexpr int SMEM_GEMM = 2048 + 3 * 65536; // 198656 (both GEMMs)

// tf32 round (sm_80+, safe on every compile pass)
__device__ __forceinline__ float tf32_rn(float a) {
    uint32_t r;
    asm("cvt.rna.tf32.f32 %0, %1;" : "=r"(r) : "f"(a));
    return __uint_as_float(r);
}

#if TC_OK
// ===========================================================================
// sm_103a helpers
// ===========================================================================
__device__ __forceinline__ uint32_t smem_u32(const void* p) {
    uint32_t a;
    asm("{ .reg .u64 t; cvta.to.shared.u64 t, %1; cvt.u32.u64 %0, t; }"
        : "=r"(a) : "l"(p));
    return a;
}
__device__ __forceinline__ uint32_t elect_one() {
    uint32_t p;
    asm volatile("{ .reg .pred p; elect.sync _|p, 0xFFFFFFFF; selp.b32 %0, 1, 0, p; }"
                 : "=r"(p));
    return p;
}
__device__ __forceinline__ void mbar_init(uint32_t addr, uint32_t cnt) {
    asm volatile("mbarrier.init.shared.b64 [%0], %1;" :: "r"(addr), "r"(cnt) : "memory");
}
__device__ __forceinline__ void mbar_wait(uint32_t mbar, int parity) {
    uint32_t done;
    asm volatile("{\n\t.reg .pred p;\n\t"
                 "mbarrier.try_wait.parity.acquire.cta.shared::cta.b64 p, [%1], %2;\n\t"
                 "selp.b32 %0, 1, 0, p;\n\t}"
                 : "=r"(done) : "r"(mbar), "r"((uint32_t)parity) : "memory");
    while (!done) {
        asm volatile("{\n\t.reg .pred p;\n\t"
                     "mbarrier.try_wait.parity.acquire.cta.shared::cta.b64 p, [%1], %2, 0x989680;\n\t"
                     "selp.b32 %0, 1, 0, p;\n\t}"
                     : "=r"(done) : "r"(mbar), "r"((uint32_t)parity) : "memory");
    }
}
__device__ __forceinline__ void mbar_expect_tx(uint32_t mbar, uint32_t bytes) {
    asm volatile("mbarrier.arrive.expect_tx.shared.b64 _, [%0], %1;"
                 :: "r"(mbar), "r"(bytes) : "memory");
}
__device__ __forceinline__ void tma2d(uint32_t dst, const CUtensorMap* map,
                                      int cx, int cy, uint32_t mbar) {
    asm volatile("cp.async.bulk.tensor.2d.shared::cta.global.tile.mbarrier::complete_tx::bytes "
                 "[%0], [%1, {%2, %3}], [%4];"
                 :: "r"(dst), "l"(map), "r"(cx), "r"(cy), "r"(mbar) : "memory");
}
__device__ __forceinline__ void tmem_alloc(uint32_t smem_dst, uint32_t ncols) {
    asm volatile("tcgen05.alloc.cta_group::1.sync.aligned.shared::cta.b32 [%0], %1;"
                 :: "r"(smem_dst), "r"(ncols) : "memory");
}
__device__ __forceinline__ void tmem_dealloc(uint32_t tmem, uint32_t ncols) {
    asm volatile("tcgen05.relinquish_alloc_permit.cta_group::1.sync.aligned;");
    asm volatile("tcgen05.dealloc.cta_group::1.sync.aligned.b32 %0, %1;" :: "r"(tmem), "r"(ncols));
}
__device__ __forceinline__ void mma_commit(uint32_t mbar) {
    asm volatile("tcgen05.commit.cta_group::1.mbarrier::arrive::one.shared::cluster.b64 [%0];"
                 :: "r"(mbar) : "memory");
}
__device__ __forceinline__ void mma_tf32_ss(uint32_t d, uint64_t a_desc, uint64_t b_desc,
                                            uint32_t idesc, uint32_t en) {
    asm volatile("{\n\t.reg .pred p;\n\tsetp.ne.u32 p, %4, 0;\n\t"
                 "tcgen05.mma.cta_group::1.kind::tf32 [%0], %1, %2, %3, p;\n\t}"
                 :: "r"(d), "l"(a_desc), "l"(b_desc), "r"(idesc), "r"(en) : "memory");
}
// SW128 K-major descriptor: LBO=1, SBO=64, layout=2, version=1.
__device__ __forceinline__ uint64_t sdesc(uint32_t addr) {
    constexpr uint64_t BASE = (2ull << 61) | (1ull << 46) | (64ull << 32) | (1ull << 16);
    return BASE | ((uint64_t)(addr >> 4) & 0x3FFFull);
}
__device__ __forceinline__ void ldtm_x32(uint32_t* r, uint32_t addr) {
    asm volatile(
        "tcgen05.ld.sync.aligned.32x32b.x32.b32 "
        "{%0, %1, %2, %3, %4, %5, %6, %7, "
        " %8, %9, %10, %11, %12, %13, %14, %15, "
        " %16, %17, %18, %19, %20, %21, %22, %23, "
        " %24, %25, %26, %27, %28, %29, %30, %31}, [%32];"
        : "=r"(r[0]),  "=r"(r[1]),  "=r"(r[2]),  "=r"(r[3]),
          "=r"(r[4]),  "=r"(r[5]),  "=r"(r[6]),  "=r"(r[7]),
          "=r"(r[8]),  "=r"(r[9]),  "=r"(r[10]), "=r"(r[11]),
          "=r"(r[12]), "=r"(r[13]), "=r"(r[14]), "=r"(r[15]),
          "=r"(r[16]), "=r"(r[17]), "=r"(r[18]), "=r"(r[19]),
          "=r"(r[20]), "=r"(r[21]), "=r"(r[22]), "=r"(r[23]),
          "=r"(r[24]), "=r"(r[25]), "=r"(r[26]), "=r"(r[27]),
          "=r"(r[28]), "=r"(r[29]), "=r"(r[30]), "=r"(r[31])
        : "r"(addr));
}
#define TCGEN05_WAIT_LD()      asm volatile("tcgen05.wait::ld.sync.aligned;" ::: "memory")
#define FENCE_ASYNC_SHARED()   asm volatile("fence.proxy.async.shared::cta;" ::: "memory")
#define TCGEN05_FENCE_AFTER()  asm volatile("tcgen05.fence::after_thread_sync;" ::: "memory")
#define TCGEN05_FENCE_BEFORE() asm volatile("tcgen05.fence::before_thread_sync;" ::: "memory")

// idesc: c=F32, a=b=TF32, K-major, N=128, M=128
static constexpr uint32_t IDESC_TF32 =
    (1u << 4) | (2u << 7) | (2u << 10) | ((128u / 8u) << 17) | ((128u / 16u) << 24);
#endif // TC_OK

// ===========================================================================
// Pre-round + reset
// ===========================================================================
__global__ void round_tf32_kernel(float* __restrict__ dst, const float* __restrict__ src,
                                  long long n) {
    long long i = ((long long)blockIdx.x * blockDim.x + threadIdx.x) * 4;
    const long long stride = (long long)gridDim.x * blockDim.x * 4;
    for (; i < n; i += stride) {
        float4 v = *(const float4*)(src + i);
        v.x = tf32_rn(v.x); v.y = tf32_rn(v.y);
        v.z = tf32_rn(v.z); v.w = tf32_rn(v.w);
        *(float4*)(dst + i) = v;
    }
}
__global__ void reset_fix_cnt() {
    if (threadIdx.x == 0 && blockIdx.x == 0) g_fix_cnt = 0;
}

// ===========================================================================
// Kernel 1: fused up+gate. Single CTA, BM=256 tokens x BN=128 neurons.
// Stage = x(32K, 256 rows) + wu(16K) + wg(16K) = 64KB, 3 stages.
// TMEM 512: up [0,128)+[128,256) (M-subtiles), gate [256,384)+[384,512).
// ===========================================================================
__global__ __launch_bounds__(256)
void upgate_mma(const __grid_constant__ CUtensorMap mx,
                const __grid_constant__ CUtensorMap mu,
                const __grid_constant__ CUtensorMap mg,
                const float* __restrict__ x, const float* __restrict__ wg,
                const float* __restrict__ wu, const float* __restrict__ avg,
                int M, int H, int I)
{
    // Supertile remap: bands of 4 bm-256 tiles, n-major inside a band.
    const int GX = gridDim.x;                    // I/128 = 112
    const int lin = blockIdx.y * GX + blockIdx.x;
    const int band = lin / (4 * GX);
    const int rr = lin - band * 4 * GX;
    const int bn = (rr >> 2) * 128;
    const int bm = (band * 4 + (rr & 3)) * 256;

#if TC_OK
    extern __shared__ __align__(1024) char smem[];
    const uint32_t sb = smem_u32(smem);
    float* avg_s = (float*)(smem + 512);
    constexpr uint32_t STAGE0 = 2048, SSZ = 65536;
    constexpr int NS = 3;
    const uint32_t FULL = sb + 16, DONE = sb + 80;

    const int tid = threadIdx.x;
    const int wid = tid >> 5;
    const int lane = tid & 31;

    if (wid == 0) tmem_alloc(sb, 512);
    if (tid == 0) {
#pragma unroll
        for (int s = 0; s < NS; ++s) { mbar_init(FULL + 8 * s, 1); mbar_init(DONE + 8 * s, 1); }
        FENCE_ASYNC_SHARED();
    }
    if (tid < 128) avg_s[tid] = avg[bn + tid];
    __syncthreads();
    const uint32_t tmem = *(volatile uint32_t*)smem;
    const int nchunks = H / 32;

    if (wid == 0) {
        int phf[NS] = {}, phd[NS] = {};
        const uint32_t e1 = elect_one();
        if (e1) {
#pragma unroll
            for (int s = 0; s < NS; ++s) {
                const uint32_t sa = sb + STAGE0 + (uint32_t)s * SSZ;
                mbar_expect_tx(FULL + 8 * s, 65536);
                tma2d(sa,         &mx, s * 32, bm, FULL + 8 * s);   // 256 rows
                tma2d(sa + 32768, &mu, s * 32, bn, FULL + 8 * s);   // 128 rows
                tma2d(sa + 49152, &mg, s * 32, bn, FULL + 8 * s);   // 128 rows
            }
        }
        int s = 0;
        for (int kt = 0; kt < nchunks; ++kt) {
            mbar_wait(FULL + 8 * s, phf[s]); phf[s] ^= 1;
            if (e1) {
                const uint32_t sa = sb + STAGE0 + (uint32_t)s * SSZ;
                const uint64_t x0 = sdesc(sa), x1 = sdesc(sa + 16384);
                const uint64_t ud = sdesc(sa + 32768), gd = sdesc(sa + 49152);
#pragma unroll
                for (int st = 0; st < 4; ++st) {
                    const uint32_t en = (kt > 0 || st > 0) ? 1u : 0u;
                    const uint64_t o = (uint64_t)(st * 2);
                    mma_tf32_ss(tmem,       x0 + o, ud + o, IDESC_TF32, en); // up   m0
                    mma_tf32_ss(tmem + 128, x1 + o, ud + o, IDESC_TF32, en); // up   m1
                    mma_tf32_ss(tmem + 256, x0 + o, gd + o, IDESC_TF32, en); // gate m0
                    mma_tf32_ss(tmem + 384, x1 + o, gd + o, IDESC_TF32, en); // gate m1
                }
                mma_commit(DONE + 8 * s);
            }
            const int tgt = kt + NS;
            if (tgt < nchunks) {
                mbar_wait(DONE + 8 * s, phd[s]); phd[s] ^= 1;
                if (e1) {
                    const uint32_t sa = sb + STAGE0 + (uint32_t)s * SSZ;
                    mbar_expect_tx(FULL + 8 * s, 65536);
                    tma2d(sa,         &mx, tgt * 32, bm, FULL + 8 * s);
                    tma2d(sa + 32768, &mu, tgt * 32, bn, FULL + 8 * s);
                    tma2d(sa + 49152, &mg, tgt * 32, bn, FULL + 8 * s);
                }
            }
            if (++s == NS) s = 0;
        }
#pragma unroll
        for (int q = 0; q < NS; ++q) mbar_wait(DONE + 8 * q, phd[q]);
    }
    __syncthreads();
    TCGEN05_FENCE_AFTER();

    // Epilogue: warps 0-3 -> M-subtile 0, warps 4-7 -> subtile 1.
    {
        const int half = wid >> 2;
        const int sub = wid & 3;
        const int token = bm + half * 128 + sub * 32 + lane;
        const uint32_t upb = tmem + half * 128;
        const uint32_t gtb = tmem + 256 + half * 128;
#pragma unroll
        for (int cc = 0; cc < 4; ++cc) {
            uint32_t ru[32], rg[32];
            ldtm_x32(ru, upb + cc * 32);
            ldtm_x32(rg, gtb + cc * 32);
            TCGEN05_WAIT_LD();
            const size_t base = (size_t)token * I + bn + cc * 32;
#pragma unroll
            for (int qq = 0; qq < 8; ++qq) {
                float4 h4;
                float* hp = (float*)&h4;
#pragma unroll
                for (int e = 0; e < 4; ++e) {
                    const int j = qq * 4 + e;
                    const float up = __uint_as_float(ru[j]);
                    const float g  = __uint_as_float(rg[j]);
                    const float a  = avg_s[cc * 32 + j];
                    const float m  = fabsf(up * a);
                    const unsigned msk = (m >= 0.5f) ? 1u : 0u;
                    float v = 0.0f;
                    if (msk) v = (g / (1.0f + expf(-g))) * up;
                    if (fabsf(m - 0.5f) < FIX_DELTA) {
                        const unsigned idx = atomicAdd(&g_fix_cnt, 1u);
                        if (idx < FIX_CAP)
                            g_fix_list[idx] = (msk << 27) | ((unsigned)token << 14)
                                            | (unsigned)(bn + cc * 32 + j);
                    }
                    hp[e] = tf32_rn(v);
                }
                *(float4*)(g_t_r + base + qq * 4) = h4;
            }
        }
    }
    TCGEN05_FENCE_BEFORE();
    __syncthreads();
    if (wid == 0) tmem_dealloc(tmem, 512);

#else // ---------------- fallback: FFMA pipeline (compute_103 pass) --------
    extern __shared__ char smem_raw[];
    constexpr int BK = 16, TM = 8, TN = 4, AST = 132, BST = 68;
    float* AsS = (float*)smem_raw;
    float* BuS = AsS + 2 * BK * AST;
    float* BgS = BuS + 2 * BK * BST;
#define A_AT(s,k,r) AsS[((s) * BK + (k)) * AST + (r)]
#define U_AT(s,k,r) BuS[((s) * BK + (k)) * BST + (r)]
#define G_AT(s,k,r) BgS[((s) * BK + (k)) * BST + (r)]
    const int tid = threadIdx.x;
    const int tx = tid & 15, ty = tid >> 4;
    const int row0 = ty * TM, col0 = tx * TN;
    const int lr = tid >> 2, lk = (tid & 3) * 4;
    const int ktiles = H / BK;
    for (int mh = 0; mh < 2; ++mh) {
        const int bmh = bm + mh * 128;
        for (int half = 0; half < 2; ++half) {
            const int bnh = bn + half * 64;
            const float* pa0 = x  + (size_t)(bmh + lr)      * H + lk;
            const float* pa1 = x  + (size_t)(bmh + lr + 64) * H + lk;
            const float* pbu = wu + (size_t)(bnh + lr)      * H + lk;
            const float* pbg = wg + (size_t)(bnh + lr)      * H + lk;
            float accU[TM][TN] = {};
            float accG[TM][TN] = {};
            {
                float4 a0 = *(const float4*)pa0;
                float4 a1 = *(const float4*)pa1;
                float4 b0 = *(const float4*)pbu;
                float4 b1 = *(const float4*)pbg;
                float av0[4] = {a0.x, a0.y, a0.z, a0.w};
                float av1[4] = {a1.x, a1.y, a1.z, a1.w};
                float bv0[4] = {b0.x, b0.y, b0.z, b0.w};
                float bv1[4] = {b1.x, b1.y, b1.z, b1.w};
#pragma unroll
                for (int e = 0; e < 4; e++) {
                    A_AT(0, lk + e, lr)      = av0[e];
                    A_AT(0, lk + e, lr + 64) = av1[e];
                    U_AT(0, lk + e, lr)      = bv0[e];
                    G_AT(0, lk + e, lr)      = bv1[e];
                }
            }
            __syncthreads();
            for (int kt = 0; kt < ktiles; ++kt) {
                const int cur = kt & 1, nxt = cur ^ 1;
                float4 na0, na1, nbu, nbg;
                const bool more = (kt + 1 < ktiles);
                if (more) {
                    const int off = (kt + 1) * BK;
                    na0 = *(const float4*)(pa0 + off);
                    na1 = *(const float4*)(pa1 + off);
                    nbu = *(const float4*)(pbu + off);
                    nbg = *(const float4*)(pbg + off);
                }
#pragma unroll
                for (int k = 0; k < BK; k++) {
                    float af[TM], uf[TN], gf[TN];
#pragma unroll
                    for (int i = 0; i < TM; i++) af[i] = A_AT(cur, k, row0 + i);
#pragma unroll
                    for (int j = 0; j < TN; j++) {
                        uf[j] = U_AT(cur, k, col0 + j);
                        gf[j] = G_AT(cur, k, col0 + j);
                    }
#pragma unroll
                    for (int i = 0; i < TM; i++)
#pragma unroll
                        for (int j = 0; j < TN; j++) {
                            accU[i][j] = fmaf(af[i], uf[j], accU[i][j]);
                            accG[i][j] = fmaf(af[i], gf[j], accG[i][j]);
                        }
                }
                if (more) {
                    float av0[4] = {na0.x, na0.y, na0.z, na0.w};
                    float av1[4] = {na1.x, na1.y, na1.z, na1.w};
                    float bv0[4] = {nbu.x, nbu.y, nbu.z, nbu.w};
                    float bv1[4] = {nbg.x, nbg.y, nbg.z, nbg.w};
#pragma unroll
                    for (int e = 0; e < 4; e++) {
                        A_AT(nxt, lk + e, lr)      = av0[e];
                        A_AT(nxt, lk + e, lr + 64) = av1[e];
                        U_AT(nxt, lk + e, lr)      = bv0[e];
                        G_AT(nxt, lk + e, lr)      = bv1[e];
                    }
                }
                __syncthreads();
            }
#pragma unroll
            for (int j = 0; j < TN; j++) {
                const int col = bnh + col0 + j;
                const float a = avg[col];
#pragma unroll
                for (int i = 0; i < TM; i++) {
                    const float up = accU[i][j];
                    const float g  = accG[i][j];
                    float v = 0.0f;
                    if (fabsf(up * a) >= 0.5f) v = (g / (1.0f + expf(-g))) * up;
                    g_t_r[(size_t)(bmh + row0 + i) * I + col] = v;
                }
            }
            __syncthreads();
        }
    }
#undef A_AT
#undef U_AT
#undef G_AT
#endif
}

// ===========================================================================
// Correction v2: recompute du exactly; act only when the exact mask differs
// from the approximate one (bit 27 of the flag word). dg row is loaded only
// on OFF->ON flips. Unchanged mask => stored approx t is already fine.
// ===========================================================================
__global__ __launch_bounds__(256)
void fix_mask_kernel(const float* __restrict__ x, const float* __restrict__ wg,
                     const float* __restrict__ wu, const float* __restrict__ avg,
                     int H, int I)
{
    const unsigned raw = g_fix_cnt;
    const unsigned n = raw < FIX_CAP ? raw : FIX_CAP;
    const unsigned warp_g = (blockIdx.x * blockDim.x + threadIdx.x) >> 5;
    const unsigned nwarps = (gridDim.x * blockDim.x) >> 5;
    const int lane = threadIdx.x & 31;

    for (unsigned i = warp_g; i < n; i += nwarps) {
        const unsigned code = g_fix_list[i];
        const unsigned amask = (code >> 27) & 1u;
        const int token  = (int)((code >> 14) & 0x1FFFu);
        const int neuron = (int)(code & 0x3FFFu);
        const float* xr = x  + (size_t)token  * H;
        const float* ur = wu + (size_t)neuron * H;

        float du = 0.0f;
        for (int k = lane * 4; k < H; k += 128) {
            const float4 xv = *(const float4*)(xr + k);
            const float4 uv = *(const float4*)(ur + k);
            du = fmaf(xv.x, uv.x, fmaf(xv.y, uv.y, fmaf(xv.z, uv.z, fmaf(xv.w, uv.w, du))));
        }
#pragma unroll
        for (int o = 16; o; o >>= 1) du += __shfl_xor_sync(0xFFFFFFFFu, du, o);

        const unsigned emask = (fabsf(du * avg[neuron]) >= 0.5f) ? 1u : 0u;
        if (emask == amask) continue;          // approx mask correct: t already fine

        if (!emask) {                          // ON -> OFF: zero it
            if (lane == 0) g_t_r[(size_t)token * I + neuron] = 0.0f;
            continue;
        }
        // OFF -> ON: need exact gate value too.
        const float* gr = wg + (size_t)neuron * H;
        float dg = 0.0f;
        for (int k = lane * 4; k < H; k += 128) {
            const float4 xv = *(const float4*)(xr + k);
            const float4 gv = *(const float4*)(gr + k);
            dg = fmaf(xv.x, gv.x, fmaf(xv.y, gv.y, fmaf(xv.z, gv.z, fmaf(xv.w, gv.w, dg))));
        }
#pragma unroll
        for (int o = 16; o; o >>= 1) dg += __shfl_xor_sync(0xFFFFFFFFu, dg, o);
        if (lane == 0) {
            const float v = (dg / (1.0f + expf(-dg))) * du;
            g_t_r[(size_t)token * I + neuron] = tf32_rn(v);
        }
    }
}

// ===========================================================================
// Kernel 2: down projection, out[M,H] = t @ wd^T. Single CTA, BM=256, BN=256.
// Stage = t(32K) + wd(32K) = 64KB, 3 stages. TMEM 512: D m0 [0,256), m1 [256,512).
// ===========================================================================
__global__ __launch_bounds__(256)
void down_mma(const __grid_constant__ CUtensorMap mt,
              const __grid_constant__ CUtensorMap mw,
              const float* __restrict__ wd, float* __restrict__ out,
              int M, int H, int I)
{
    const int GX = gridDim.x;                    // H/256 = 16
    const int lin = blockIdx.y * GX + blockIdx.x;
    const int band = lin / (4 * GX);
    const int rr = lin - band * 4 * GX;
    const int bn = (rr >> 2) * 256;
    const int bm = (band * 4 + (rr & 3)) * 256;

#if TC_OK
    extern __shared__ __align__(1024) char smem[];
    const uint32_t sb = smem_u32(smem);
    constexpr uint32_t STAGE0 = 2048, SSZ = 65536;
    constexpr int NS = 3;
    const uint32_t FULL = sb + 16, DONE = sb + 80;

    const int tid = threadIdx.x;
    const int wid = tid >> 5;
    const int lane = tid & 31;

    if (wid == 0) tmem_alloc(sb, 512);
    if (tid == 0) {
#pragma unroll
        for (int s = 0; s < NS; ++s) { mbar_init(FULL + 8 * s, 1); mbar_init(DONE + 8 * s, 1); }
        FENCE_ASYNC_SHARED();
    }
    __syncthreads();
    const uint32_t tmem = *(volatile uint32_t*)smem;
    const int nchunks = I / 32;

    if (wid == 0) {
        int phf[NS] = {}, phd[NS] = {};
        const uint32_t e1 = elect_one();
        if (e1) {
#pragma unroll
            for (int s = 0; s < NS; ++s) {
                const uint32_t sa = sb + STAGE0 + (uint32_t)s * SSZ;
                mbar_expect_tx(FULL + 8 * s, 65536);
                tma2d(sa,         &mt, s * 32, bm, FULL + 8 * s);   // t  256 rows
                tma2d(sa + 32768, &mw, s * 32, bn, FULL + 8 * s);   // wd 256 rows
            }
        }
        int s = 0;
        for (int kt = 0; kt < nchunks; ++kt) {
            mbar_wait(FULL + 8 * s, phf[s]); phf[s] ^= 1;
            if (e1) {
                const uint32_t sa = sb + STAGE0 + (uint32_t)s * SSZ;
                const uint64_t t0 = sdesc(sa),         t1 = sdesc(sa + 16384);
                const uint64_t w0 = sdesc(sa + 32768), w1 = sdesc(sa + 49152);
#pragma unroll
                for (int st = 0; st < 4; ++st) {
                    const uint32_t en = (kt > 0 || st > 0) ? 1u : 0u;
                    const uint64_t o = (uint64_t)(st * 2);
                    mma_tf32_ss(tmem,       t0 + o, w0 + o, IDESC_TF32, en);
                    mma_tf32_ss(tmem + 128, t0 + o, w1 + o, IDESC_TF32, en);
                    mma_tf32_ss(tmem + 256, t1 + o, w0 + o, IDESC_TF32, en);
                    mma_tf32_ss(tmem + 384, t1 + o, w1 + o, IDESC_TF32, en);
                }
                mma_commit(DONE + 8 * s);
            }
            const int tgt = kt + NS;
            if (tgt < nchunks) {
                mbar_wait(DONE + 8 * s, phd[s]); phd[s] ^= 1;
                if (e1) {
                    const uint32_t sa = sb + STAGE0 + (uint32_t)s * SSZ;
                    mbar_expect_tx(FULL + 8 * s, 65536);
                    tma2d(sa,         &mt, tgt * 32, bm, FULL + 8 * s);
                    tma2d(sa + 32768, &mw, tgt * 32, bn, FULL + 8 * s);
                }
            }
            if (++s == NS) s = 0;
        }
#pragma unroll
        for (int q = 0; q < NS; ++q) mbar_wait(DONE + 8 * q, phd[q]);
    }
    __syncthreads();
    TCGEN05_FENCE_AFTER();

    {
        const int half = wid >> 2;
        const int sub = wid & 3;
        const int token = bm + half * 128 + sub * 32 + lane;
        const uint32_t db = tmem + half * 256;
#pragma unroll
        for (int cc = 0; cc < 8; ++cc) {
            uint32_t r[32];
            ldtm_x32(r, db + cc * 32);
            TCGEN05_WAIT_LD();
            const size_t base = (size_t)token * H + bn + cc * 32;
#pragma unroll
            for (int q = 0; q < 8; ++q) {
                float4 v4;
                ((float*)&v4)[0] = __uint_as_float(r[q * 4 + 0]);
                ((float*)&v4)[1] = __uint_as_float(r[q * 4 + 1]);
                ((float*)&v4)[2] = __uint_as_float(r[q * 4 + 2]);
                ((float*)&v4)[3] = __uint_as_float(r[q * 4 + 3]);
                *(float4*)(out + base + q * 4) = v4;
            }
        }
    }
    TCGEN05_FENCE_BEFORE();
    __syncthreads();
    if (wid == 0) tmem_dealloc(tmem, 512);

#else // ---------------- fallback: FFMA down (4 subtiles) ------------------
    extern __shared__ char smem_raw[];
    constexpr int BK = 16, TM = 8, TN = 8, AST = 132;
    float* AsS = (float*)smem_raw;
    float* BsS = AsS + 2 * BK * AST;
#define A_AT(s,k,r) AsS[((s) * BK + (k)) * AST + (r)]
#define B_AT(s,k,r) BsS[((s) * BK + (k)) * AST + (r)]
    const int tid = threadIdx.x;
    const int tx = tid & 15, ty = tid >> 4;
    const int row0 = ty * TM, col0 = tx * TN;
    const int lr = tid >> 2, lk = (tid & 3) * 4;
    const int ktiles = I / BK;
    for (int mh = 0; mh < 2; ++mh) {
        const int bmh = bm + mh * 128;
        for (int half = 0; half < 2; ++half) {
            const int bnh = bn + half * 128;
            const float* pa0 = g_t_r + (size_t)(bmh + lr)      * I + lk;
            const float* pa1 = g_t_r + (size_t)(bmh + lr + 64) * I + lk;
            const float* pb0 = wd    + (size_t)(bnh + lr)      * I + lk;
            const float* pb1 = wd    + (size_t)(bnh + lr + 64) * I + lk;
            float acc[TM][TN] = {};
            {
                float4 a0 = *(const float4*)pa0;
                float4 a1 = *(const float4*)pa1;
                float4 b0 = *(const float4*)pb0;
                float4 b1 = *(const float4*)pb1;
                float av0[4] = {a0.x, a0.y, a0.z, a0.w};
                float av1[4] = {a1.x, a1.y, a1.z, a1.w};
                float bv0[4] = {b0.x, b0.y, b0.z, b0.w};
                float bv1[4] = {b1.x, b1.y, b1.z, b1.w};
#pragma unroll
                for (int e = 0; e < 4; e++) {
                    A_AT(0, lk + e, lr)      = av0[e];
                    A_AT(0, lk + e, lr + 64) = av1[e];
                    B_AT(0, lk + e, lr)      = bv0[e];
                    B_AT(0, lk + e, lr + 64) = bv1[e];
                }
            }
            __syncthreads();
            for (int kt = 0; kt < ktiles; ++kt) {
                const int cur = kt & 1, nxt = cur ^ 1;
                float4 na0, na1, nb0, nb1;
                const bool more = (kt + 1 < ktiles);
                if (more) {
                    const int off = (kt + 1) * BK;
                    na0 = *(const float4*)(pa0 + off);
                    na1 = *(const float4*)(pa1 + off);
                    nb0 = *(const float4*)(pb0 + off);
                    nb1 = *(const float4*)(pb1 + off);
                }
#pragma unroll
                for (int k = 0; k < BK; k++) {
                    float af[TM], bf[TN];
#pragma unroll
                    for (int i = 0; i < TM; i++) af[i] = A_AT(cur, k, row0 + i);
#pragma unroll
                    for (int j = 0; j < TN; j++) bf[j] = B_AT(cur, k, col0 + j);
#pragma unroll
                    for (int i = 0; i < TM; i++)
#pragma unroll
                        for (int j = 0; j < TN; j++)
                            acc[i][j] = fmaf(af[i], bf[j], acc[i][j]);
                }
                if (more) {
                    float av0[4] = {na0.x, na0.y, na0.z, na0.w};
                    float av1[4] = {na1.x, na1.y, na1.z, na1.w};
                    float bv0[4] = {nb0.x, nb0.y, nb0.z, nb0.w};
                    float bv1[4] = {nb1.x, nb1.y, nb1.z, nb1.w};
#pragma unroll
                    for (int e = 0; e < 4; e++) {
                        A_AT(nxt, lk + e, lr)      = av0[e];
                        A_AT(nxt, lk + e, lr + 64) = av1[e];
                        B_AT(nxt, lk + e, lr)      = bv0[e];
                        B_AT(nxt, lk + e, lr + 64) = bv1[e];
                    }
                }
                __syncthreads();
            }
#pragma unroll
            for (int i = 0; i < TM; i++) {
                const size_t rbase = (size_t)(bmh + row0 + i) * H + bnh + col0;
#pragma unroll
                for (int j = 0; j < TN; j++) out[rbase + j] = acc[i][j];
            }
            __syncthreads();
        }
    }
#undef A_AT
#undef B_AT
#endif
}

// ---------------------------------------------------------------------------
// Launch: pre-round -> reset -> upgate(+flag) -> fix -> down
// ---------------------------------------------------------------------------
typedef CUresult (CUDAAPI *EncodeFn)(CUtensorMap*, CUtensorMapDataType, cuuint32_t, void*,
    const cuuint64_t*, const cuuint64_t*, const cuuint32_t*, const cuuint32_t*,
    CUtensorMapInterleave, CUtensorMapSwizzle, CUtensorMapL2promotion, CUtensorMapFloatOOBfill);

extern "C" void kernel_launch(void* const* d_in, const int* in_sizes, int n_in,
                              void* d_out, int out_size)
{
    const float* x   = (const float*)d_in[0];
    const float* wg  = (const float*)d_in[1];
    const float* wu  = (const float*)d_in[2];
    const float* wd  = (const float*)d_in[3];
    const float* avg = (const float*)d_in[4];
    float* out = (float*)d_out;

    const int I = in_sizes[4];            // 14336
    const int H = in_sizes[3] / I;        // 4096
    const int M = in_sizes[0] / H;        // 8192

    cudaFuncSetAttribute(upgate_mma, cudaFuncAttributeMaxDynamicSharedMemorySize, SMEM_GEMM);
    cudaFuncSetAttribute(down_mma,   cudaFuncAttributeMaxDynamicSharedMemorySize, SMEM_GEMM);

    float *xr, *wur, *wgr, *wdr, *tr;
    cudaGetSymbolAddress((void**)&xr,  g_x_r);
    cudaGetSymbolAddress((void**)&wur, g_wu_r);
    cudaGetSymbolAddress((void**)&wgr, g_wg_r);
    cudaGetSymbolAddress((void**)&wdr, g_wd_r);
    cudaGetSymbolAddress((void**)&tr,  g_t_r);

    static EncodeFn enc = nullptr;
    if (!enc) {
        void* fp = nullptr;
        cudaDriverEntryPointQueryResult qr;
        cudaGetDriverEntryPoint("cuTensorMapEncodeTiled", &fp, cudaEnableDefault, &qr);
        enc = (EncodeFn)fp;
    }
    CUtensorMap mx, mu, mg, mt, mw;
    auto mk = [&](CUtensorMap* m, void* ptr, unsigned long long inner,
                  unsigned long long rows, unsigned boxRows) {
        cuuint64_t dims[2]    = {inner, rows};
        cuuint64_t strides[1] = {inner * 4};
        cuuint32_t box[2]     = {32u, boxRows};
        cuuint32_t es[2]      = {1u, 1u};
        enc(m, CU_TENSOR_MAP_DATA_TYPE_FLOAT32, 2, ptr, dims, strides, box, es,
            CU_TENSOR_MAP_INTERLEAVE_NONE, CU_TENSOR_MAP_SWIZZLE_128B,
            CU_TENSOR_MAP_L2_PROMOTION_L2_128B, CU_TENSOR_MAP_FLOAT_OOB_FILL_NONE);
    };
    mk(&mx, xr,  (unsigned long long)H, (unsigned long long)M, 256u);
    mk(&mu, wur, (unsigned long long)H, (unsigned long long)I, 128u);
    mk(&mg, wgr, (unsigned long long)H, (unsigned long long)I, 128u);
    mk(&mt, tr,  (unsigned long long)I, (unsigned long long)M, 256u);
    mk(&mw, wdr, (unsigned long long)I, (unsigned long long)H, 256u);

    round_tf32_kernel<<<2048, 256>>>(xr,  x,  (long long)M * H);
    round_tf32_kernel<<<2048, 256>>>(wur, wu, (long long)I * H);
    round_tf32_kernel<<<2048, 256>>>(wgr, wg, (long long)I * H);
    round_tf32_kernel<<<2048, 256>>>(wdr, wd, (long long)H * I);
    reset_fix_cnt<<<1, 32>>>();

    dim3 g1(I / 128, M / 256);            // 112 x 32
    upgate_mma<<<g1, 256, SMEM_GEMM>>>(mx, mu, mg, x, wg, wu, avg, M, H, I);

    fix_mask_kernel<<<2048, 256>>>(x, wg, wu, avg, H, I);

    dim3 g2(H / 256, M / 256);            // 16 x 32
    down_mma<<<g2, 256, SMEM_GEMM>>>(mt, mw, wd, out, M, H, I);
}

// round 12
// speedup vs baseline: 1.0691x; 1.0691x over previous
#include <cuda_runtime.h>
#include <cuda.h>
#include <math.h>
#include <stdint.h>

// ---------------------------------------------------------------------------
// Feature detection: tcgen05/TMA-tensor are arch-SPECIFIC (sm_103a / sm_100a).
// ---------------------------------------------------------------------------
#ifdef __CUDA_ARCH_HAS_FEATURE__
#define TC_FEAT_103 __CUDA_ARCH_HAS_FEATURE__(SM103_ALL)
#define TC_FEAT_100 __CUDA_ARCH_HAS_FEATURE__(SM100_ALL)
#else
#define TC_FEAT_103 0
#define TC_FEAT_100 0
#endif
#if defined(__CUDA_ARCH__) && (TC_FEAT_103 || TC_FEAT_100 || \
    defined(__CUDA_ARCH_FEAT_SM103_ALL) || defined(__CUDA_ARCH_FEAT_SM100_ALL))
#define TC_OK 1
#else
#define TC_OK 0
#endif

// ---------------------------------------------------------------------------
// Global scratch (static; no allocations allowed).
// ---------------------------------------------------------------------------
static __device__ float g_t_r [117440512ull]; // 8192*14336 (tf32-rounded t)
static __device__ float g_x_r [33554432ull];  // 8192*4096
static __device__ float g_wu_r[58720256ull];  // 14336*4096
static __device__ float g_wg_r[58720256ull];
static __device__ float g_wd_r[58720256ull];  // 4096*14336
static constexpr unsigned FIX_CAP = 8388608u;
static __device__ unsigned g_fix_cnt;
static __device__ unsigned g_fix_list[FIX_CAP];

// Flag word layout: bit27 = approx mask, bits[14..26] = token, bits[0..13] = neuron.
#define FIX_DELTA 1.5e-3f
static constexpr int SMEM_GEMM = 2048 + 3 * 65536; // 198656 (both GEMMs)

// tf32 round (sm_80+, safe on every compile pass)
__device__ __forceinline__ float tf32_rn(float a) {
    uint32_t r;
    asm("cvt.rna.tf32.f32 %0, %1;" : "=r"(r) : "f"(a));
    return __uint_as_float(r);
}

// Fast silu: g * sigmoid(g) using hardware EX2. |rel err| ~1e-5, far below the
// TF32 noise floor (3.6e-4) and the flag window.
__device__ __forceinline__ float fast_silu_times(float g, float up) {
    return (g / (1.0f + __expf(-g))) * up;
}

#if TC_OK
// ===========================================================================
// sm_103a helpers
// ===========================================================================
__device__ __forceinline__ uint32_t smem_u32(const void* p) {
    uint32_t a;
    asm("{ .reg .u64 t; cvta.to.shared.u64 t, %1; cvt.u32.u64 %0, t; }"
        : "=r"(a) : "l"(p));
    return a;
}
__device__ __forceinline__ uint32_t elect_one() {
    uint32_t p;
    asm volatile("{ .reg .pred p; elect.sync _|p, 0xFFFFFFFF; selp.b32 %0, 1, 0, p; }"
                 : "=r"(p));
    return p;
}
__device__ __forceinline__ void mbar_init(uint32_t addr, uint32_t cnt) {
    asm volatile("mbarrier.init.shared.b64 [%0], %1;" :: "r"(addr), "r"(cnt) : "memory");
}
__device__ __forceinline__ void mbar_wait(uint32_t mbar, int parity) {
    uint32_t done;
    asm volatile("{\n\t.reg .pred p;\n\t"
                 "mbarrier.try_wait.parity.acquire.cta.shared::cta.b64 p, [%1], %2;\n\t"
                 "selp.b32 %0, 1, 0, p;\n\t}"
                 : "=r"(done) : "r"(mbar), "r"((uint32_t)parity) : "memory");
    while (!done) {
        asm volatile("{\n\t.reg .pred p;\n\t"
                     "mbarrier.try_wait.parity.acquire.cta.shared::cta.b64 p, [%1], %2, 0x989680;\n\t"
                     "selp.b32 %0, 1, 0, p;\n\t}"
                     : "=r"(done) : "r"(mbar), "r"((uint32_t)parity) : "memory");
    }
}
__device__ __forceinline__ void mbar_expect_tx(uint32_t mbar, uint32_t bytes) {
    asm volatile("mbarrier.arrive.expect_tx.shared.b64 _, [%0], %1;"
                 :: "r"(mbar), "r"(bytes) : "memory");
}
__device__ __forceinline__ void tma2d(uint32_t dst, const CUtensorMap* map,
                                      int cx, int cy, uint32_t mbar) {
    asm volatile("cp.async.bulk.tensor.2d.shared::cta.global.tile.mbarrier::complete_tx::bytes "
                 "[%0], [%1, {%2, %3}], [%4];"
                 :: "r"(dst), "l"(map), "r"(cx), "r"(cy), "r"(mbar) : "memory");
}
__device__ __forceinline__ void tmem_alloc(uint32_t smem_dst, uint32_t ncols) {
    asm volatile("tcgen05.alloc.cta_group::1.sync.aligned.shared::cta.b32 [%0], %1;"
                 :: "r"(smem_dst), "r"(ncols) : "memory");
}
__device__ __forceinline__ void tmem_dealloc(uint32_t tmem, uint32_t ncols) {
    asm volatile("tcgen05.relinquish_alloc_permit.cta_group::1.sync.aligned;");
    asm volatile("tcgen05.dealloc.cta_group::1.sync.aligned.b32 %0, %1;" :: "r"(tmem), "r"(ncols));
}
__device__ __forceinline__ void mma_commit(uint32_t mbar) {
    asm volatile("tcgen05.commit.cta_group::1.mbarrier::arrive::one.shared::cluster.b64 [%0];"
                 :: "r"(mbar) : "memory");
}
__device__ __forceinline__ void mma_tf32_ss(uint32_t d, uint64_t a_desc, uint64_t b_desc,
                                            uint32_t idesc, uint32_t en) {
    asm volatile("{\n\t.reg .pred p;\n\tsetp.ne.u32 p, %4, 0;\n\t"
                 "tcgen05.mma.cta_group::1.kind::tf32 [%0], %1, %2, %3, p;\n\t}"
                 :: "r"(d), "l"(a_desc), "l"(b_desc), "r"(idesc), "r"(en) : "memory");
}
// SW128 K-major descriptor: LBO=1, SBO=64, layout=2, version=1.
__device__ __forceinline__ uint64_t sdesc(uint32_t addr) {
    constexpr uint64_t BASE = (2ull << 61) | (1ull << 46) | (64ull << 32) | (1ull << 16);
    return BASE | ((uint64_t)(addr >> 4) & 0x3FFFull);
}
__device__ __forceinline__ void ldtm_x32(uint32_t* r, uint32_t addr) {
    asm volatile(
        "tcgen05.ld.sync.aligned.32x32b.x32.b32 "
        "{%0, %1, %2, %3, %4, %5, %6, %7, "
        " %8, %9, %10, %11, %12, %13, %14, %15, "
        " %16, %17, %18, %19, %20, %21, %22, %23, "
        " %24, %25, %26, %27, %28, %29, %30, %31}, [%32];"
        : "=r"(r[0]),  "=r"(r[1]),  "=r"(r[2]),  "=r"(r[3]),
          "=r"(r[4]),  "=r"(r[5]),  "=r"(r[6]),  "=r"(r[7]),
          "=r"(r[8]),  "=r"(r[9]),  "=r"(r[10]), "=r"(r[11]),
          "=r"(r[12]), "=r"(r[13]), "=r"(r[14]), "=r"(r[15]),
          "=r"(r[16]), "=r"(r[17]), "=r"(r[18]), "=r"(r[19]),
          "=r"(r[20]), "=r"(r[21]), "=r"(r[22]), "=r"(r[23]),
          "=r"(r[24]), "=r"(r[25]), "=r"(r[26]), "=r"(r[27]),
          "=r"(r[28]), "=r"(r[29]), "=r"(r[30]), "=r"(r[31])
        : "r"(addr));
}
#define TCGEN05_WAIT_LD()      asm volatile("tcgen05.wait::ld.sync.aligned;" ::: "memory")
#define FENCE_ASYNC_SHARED()   asm volatile("fence.proxy.async.shared::cta;" ::: "memory")
#define TCGEN05_FENCE_AFTER()  asm volatile("tcgen05.fence::after_thread_sync;" ::: "memory")
#define TCGEN05_FENCE_BEFORE() asm volatile("tcgen05.fence::before_thread_sync;" ::: "memory")

// idesc: c=F32, a=b=TF32, K-major, N=128, M=128
static constexpr uint32_t IDESC_TF32 =
    (1u << 4) | (2u << 7) | (2u << 10) | ((128u / 8u) << 17) | ((128u / 16u) << 24);
#endif // TC_OK

// ===========================================================================
// Pre-round + reset
// ===========================================================================
__global__ void round_tf32_kernel(float* __restrict__ dst, const float* __restrict__ src,
                                  long long n) {
    long long i = ((long long)blockIdx.x * blockDim.x + threadIdx.x) * 4;
    const long long stride = (long long)gridDim.x * blockDim.x * 4;
    for (; i < n; i += stride) {
        float4 v = *(const float4*)(src + i);
        v.x = tf32_rn(v.x); v.y = tf32_rn(v.y);
        v.z = tf32_rn(v.z); v.w = tf32_rn(v.w);
        *(float4*)(dst + i) = v;
    }
}
__global__ void reset_fix_cnt() {
    if (threadIdx.x == 0 && blockIdx.x == 0) g_fix_cnt = 0;
}

// ===========================================================================
// Kernel 1: fused up+gate. Single CTA, BM=256 tokens x BN=128 neurons.
// Stage = x(32K, 256 rows) + wu(16K) + wg(16K) = 64KB, 3 stages.
// TMEM 512: up [0,128)+[128,256) (M-subtiles), gate [256,384)+[384,512).
// ===========================================================================
__global__ __launch_bounds__(256)
void upgate_mma(const __grid_constant__ CUtensorMap mx,
                const __grid_constant__ CUtensorMap mu,
                const __grid_constant__ CUtensorMap mg,
                const float* __restrict__ x, const float* __restrict__ wg,
                const float* __restrict__ wu, const float* __restrict__ avg,
                int M, int H, int I)
{
    // Supertile remap: bands of 4 bm-256 tiles, n-major inside a band.
    const int GX = gridDim.x;                    // I/128 = 112
    const int lin = blockIdx.y * GX + blockIdx.x;
    const int band = lin / (4 * GX);
    const int rr = lin - band * 4 * GX;
    const int bn = (rr >> 2) * 128;
    const int bm = (band * 4 + (rr & 3)) * 256;

#if TC_OK
    extern __shared__ __align__(1024) char smem[];
    const uint32_t sb = smem_u32(smem);
    float* avg_s = (float*)(smem + 512);
    constexpr uint32_t STAGE0 = 2048, SSZ = 65536;
    constexpr int NS = 3;
    const uint32_t FULL = sb + 16, DONE = sb + 80;

    const int tid = threadIdx.x;
    const int wid = tid >> 5;
    const int lane = tid & 31;

    if (wid == 0) tmem_alloc(sb, 512);
    if (tid == 0) {
#pragma unroll
        for (int s = 0; s < NS; ++s) { mbar_init(FULL + 8 * s, 1); mbar_init(DONE + 8 * s, 1); }
        FENCE_ASYNC_SHARED();
    }
    if (tid < 128) avg_s[tid] = avg[bn + tid];
    __syncthreads();
    const uint32_t tmem = *(volatile uint32_t*)smem;
    const int nchunks = H / 32;

    if (wid == 0) {
        int phf[NS] = {}, phd[NS] = {};
        const uint32_t e1 = elect_one();
        if (e1) {
#pragma unroll
            for (int s = 0; s < NS; ++s) {
                const uint32_t sa = sb + STAGE0 + (uint32_t)s * SSZ;
                mbar_expect_tx(FULL + 8 * s, 65536);
                tma2d(sa,         &mx, s * 32, bm, FULL + 8 * s);   // 256 rows
                tma2d(sa + 32768, &mu, s * 32, bn, FULL + 8 * s);   // 128 rows
                tma2d(sa + 49152, &mg, s * 32, bn, FULL + 8 * s);   // 128 rows
            }
        }
        int s = 0;
        for (int kt = 0; kt < nchunks; ++kt) {
            mbar_wait(FULL + 8 * s, phf[s]); phf[s] ^= 1;
            if (e1) {
                const uint32_t sa = sb + STAGE0 + (uint32_t)s * SSZ;
                const uint64_t x0 = sdesc(sa), x1 = sdesc(sa + 16384);
                const uint64_t ud = sdesc(sa + 32768), gd = sdesc(sa + 49152);
#pragma unroll
                for (int st = 0; st < 4; ++st) {
                    const uint32_t en = (kt > 0 || st > 0) ? 1u : 0u;
                    const uint64_t o = (uint64_t)(st * 2);
                    mma_tf32_ss(tmem,       x0 + o, ud + o, IDESC_TF32, en); // up   m0
                    mma_tf32_ss(tmem + 128, x1 + o, ud + o, IDESC_TF32, en); // up   m1
                    mma_tf32_ss(tmem + 256, x0 + o, gd + o, IDESC_TF32, en); // gate m0
                    mma_tf32_ss(tmem + 384, x1 + o, gd + o, IDESC_TF32, en); // gate m1
                }
                mma_commit(DONE + 8 * s);
            }
            const int tgt = kt + NS;
            if (tgt < nchunks) {
                mbar_wait(DONE + 8 * s, phd[s]); phd[s] ^= 1;
                if (e1) {
                    const uint32_t sa = sb + STAGE0 + (uint32_t)s * SSZ;
                    mbar_expect_tx(FULL + 8 * s, 65536);
                    tma2d(sa,         &mx, tgt * 32, bm, FULL + 8 * s);
                    tma2d(sa + 32768, &mu, tgt * 32, bn, FULL + 8 * s);
                    tma2d(sa + 49152, &mg, tgt * 32, bn, FULL + 8 * s);
                }
            }
            if (++s == NS) s = 0;
        }
#pragma unroll
        for (int q = 0; q < NS; ++q) mbar_wait(DONE + 8 * q, phd[q]);
    }
    __syncthreads();
    TCGEN05_FENCE_AFTER();

    // Epilogue: warps 0-3 -> M-subtile 0, warps 4-7 -> subtile 1. Fast silu.
    {
        const int half = wid >> 2;
        const int sub = wid & 3;
        const int token = bm + half * 128 + sub * 32 + lane;
        const uint32_t upb = tmem + half * 128;
        const uint32_t gtb = tmem + 256 + half * 128;
#pragma unroll
        for (int cc = 0; cc < 4; ++cc) {
            uint32_t ru[32], rg[32];
            ldtm_x32(ru, upb + cc * 32);
            ldtm_x32(rg, gtb + cc * 32);
            TCGEN05_WAIT_LD();
            const size_t base = (size_t)token * I + bn + cc * 32;
#pragma unroll
            for (int qq = 0; qq < 8; ++qq) {
                float4 h4;
                float* hp = (float*)&h4;
#pragma unroll
                for (int e = 0; e < 4; ++e) {
                    const int j = qq * 4 + e;
                    const float up = __uint_as_float(ru[j]);
                    const float g  = __uint_as_float(rg[j]);
                    const float a  = avg_s[cc * 32 + j];
                    const float m  = fabsf(up * a);
                    const unsigned msk = (m >= 0.5f) ? 1u : 0u;
                    float v = 0.0f;
                    if (msk) v = fast_silu_times(g, up);
                    if (fabsf(m - 0.5f) < FIX_DELTA) {
                        const unsigned idx = atomicAdd(&g_fix_cnt, 1u);
                        if (idx < FIX_CAP)
                            g_fix_list[idx] = (msk << 27) | ((unsigned)token << 14)
                                            | (unsigned)(bn + cc * 32 + j);
                    }
                    hp[e] = tf32_rn(v);
                }
                *(float4*)(g_t_r + base + qq * 4) = h4;
            }
        }
    }
    TCGEN05_FENCE_BEFORE();
    __syncthreads();
    if (wid == 0) tmem_dealloc(tmem, 512);

#else // ---------------- fallback: FFMA pipeline (compute_103 pass) --------
    extern __shared__ char smem_raw[];
    constexpr int BK = 16, TM = 8, TN = 4, AST = 132, BST = 68;
    float* AsS = (float*)smem_raw;
    float* BuS = AsS + 2 * BK * AST;
    float* BgS = BuS + 2 * BK * BST;
#define A_AT(s,k,r) AsS[((s) * BK + (k)) * AST + (r)]
#define U_AT(s,k,r) BuS[((s) * BK + (k)) * BST + (r)]
#define G_AT(s,k,r) BgS[((s) * BK + (k)) * BST + (r)]
    const int tid = threadIdx.x;
    const int tx = tid & 15, ty = tid >> 4;
    const int row0 = ty * TM, col0 = tx * TN;
    const int lr = tid >> 2, lk = (tid & 3) * 4;
    const int ktiles = H / BK;
    for (int mh = 0; mh < 2; ++mh) {
        const int bmh = bm + mh * 128;
        for (int half = 0; half < 2; ++half) {
            const int bnh = bn + half * 64;
            const float* pa0 = x  + (size_t)(bmh + lr)      * H + lk;
            const float* pa1 = x  + (size_t)(bmh + lr + 64) * H + lk;
            const float* pbu = wu + (size_t)(bnh + lr)      * H + lk;
            const float* pbg = wg + (size_t)(bnh + lr)      * H + lk;
            float accU[TM][TN] = {};
            float accG[TM][TN] = {};
            {
                float4 a0 = *(const float4*)pa0;
                float4 a1 = *(const float4*)pa1;
                float4 b0 = *(const float4*)pbu;
                float4 b1 = *(const float4*)pbg;
                float av0[4] = {a0.x, a0.y, a0.z, a0.w};
                float av1[4] = {a1.x, a1.y, a1.z, a1.w};
                float bv0[4] = {b0.x, b0.y, b0.z, b0.w};
                float bv1[4] = {b1.x, b1.y, b1.z, b1.w};
#pragma unroll
                for (int e = 0; e < 4; e++) {
                    A_AT(0, lk + e, lr)      = av0[e];
                    A_AT(0, lk + e, lr + 64) = av1[e];
                    U_AT(0, lk + e, lr)      = bv0[e];
                    G_AT(0, lk + e, lr)      = bv1[e];
                }
            }
            __syncthreads();
            for (int kt = 0; kt < ktiles; ++kt) {
                const int cur = kt & 1, nxt = cur ^ 1;
                float4 na0, na1, nbu, nbg;
                const bool more = (kt + 1 < ktiles);
                if (more) {
                    const int off = (kt + 1) * BK;
                    na0 = *(const float4*)(pa0 + off);
                    na1 = *(const float4*)(pa1 + off);
                    nbu = *(const float4*)(pbu + off);
                    nbg = *(const float4*)(pbg + off);
                }
#pragma unroll
                for (int k = 0; k < BK; k++) {
                    float af[TM], uf[TN], gf[TN];
#pragma unroll
                    for (int i = 0; i < TM; i++) af[i] = A_AT(cur, k, row0 + i);
#pragma unroll
                    for (int j = 0; j < TN; j++) {
                        uf[j] = U_AT(cur, k, col0 + j);
                        gf[j] = G_AT(cur, k, col0 + j);
                    }
#pragma unroll
                    for (int i = 0; i < TM; i++)
#pragma unroll
                        for (int j = 0; j < TN; j++) {
                            accU[i][j] = fmaf(af[i], uf[j], accU[i][j]);
                            accG[i][j] = fmaf(af[i], gf[j], accG[i][j]);
                        }
                }
                if (more) {
                    float av0[4] = {na0.x, na0.y, na0.z, na0.w};
                    float av1[4] = {na1.x, na1.y, na1.z, na1.w};
                    float bv0[4] = {nbu.x, nbu.y, nbu.z, nbu.w};
                    float bv1[4] = {nbg.x, nbg.y, nbg.z, nbg.w};
#pragma unroll
                    for (int e = 0; e < 4; e++) {
                        A_AT(nxt, lk + e, lr)      = av0[e];
                        A_AT(nxt, lk + e, lr + 64) = av1[e];
                        U_AT(nxt, lk + e, lr)      = bv0[e];
                        G_AT(nxt, lk + e, lr)      = bv1[e];
                    }
                }
                __syncthreads();
            }
#pragma unroll
            for (int j = 0; j < TN; j++) {
                const int col = bnh + col0 + j;
                const float a = avg[col];
#pragma unroll
                for (int i = 0; i < TM; i++) {
                    const float up = accU[i][j];
                    const float g  = accG[i][j];
                    float v = 0.0f;
                    if (fabsf(up * a) >= 0.5f) v = (g / (1.0f + expf(-g))) * up;
                    g_t_r[(size_t)(bmh + row0 + i) * I + col] = v;
                }
            }
            __syncthreads();
        }
    }
#undef A_AT
#undef U_AT
#undef G_AT
#endif
}

// ===========================================================================
// Correction v2: recompute du exactly; act only when the exact mask differs
// from the approximate one (bit 27). dg row loaded only on OFF->ON flips.
// ===========================================================================
__global__ __launch_bounds__(256)
void fix_mask_kernel(const float* __restrict__ x, const float* __restrict__ wg,
                     const float* __restrict__ wu, const float* __restrict__ avg,
                     int H, int I)
{
    const unsigned raw = g_fix_cnt;
    const unsigned n = raw < FIX_CAP ? raw : FIX_CAP;
    const unsigned warp_g = (blockIdx.x * blockDim.x + threadIdx.x) >> 5;
    const unsigned nwarps = (gridDim.x * blockDim.x) >> 5;
    const int lane = threadIdx.x & 31;

    for (unsigned i = warp_g; i < n; i += nwarps) {
        const unsigned code = g_fix_list[i];
        const unsigned amask = (code >> 27) & 1u;
        const int token  = (int)((code >> 14) & 0x1FFFu);
        const int neuron = (int)(code & 0x3FFFu);
        const float* xr = x  + (size_t)token  * H;
        const float* ur = wu + (size_t)neuron * H;

        float du = 0.0f;
        for (int k = lane * 4; k < H; k += 128) {
            const float4 xv = *(const float4*)(xr + k);
            const float4 uv = *(const float4*)(ur + k);
            du = fmaf(xv.x, uv.x, fmaf(xv.y, uv.y, fmaf(xv.z, uv.z, fmaf(xv.w, uv.w, du))));
        }
#pragma unroll
        for (int o = 16; o; o >>= 1) du += __shfl_xor_sync(0xFFFFFFFFu, du, o);

        const unsigned emask = (fabsf(du * avg[neuron]) >= 0.5f) ? 1u : 0u;
        if (emask == amask) continue;          // approx mask correct: t already fine

        if (!emask) {                          // ON -> OFF: zero it
            if (lane == 0) g_t_r[(size_t)token * I + neuron] = 0.0f;
            continue;
        }
        // OFF -> ON: need exact gate value too.
        const float* gr = wg + (size_t)neuron * H;
        float dg = 0.0f;
        for (int k = lane * 4; k < H; k += 128) {
            const float4 xv = *(const float4*)(xr + k);
            const float4 gv = *(const float4*)(gr + k);
            dg = fmaf(xv.x, gv.x, fmaf(xv.y, gv.y, fmaf(xv.z, gv.z, fmaf(xv.w, gv.w, dg))));
        }
#pragma unroll
        for (int o = 16; o; o >>= 1) dg += __shfl_xor_sync(0xFFFFFFFFu, dg, o);
        if (lane == 0) {
            const float v = (dg / (1.0f + __expf(-dg))) * du;
            g_t_r[(size_t)token * I + neuron] = tf32_rn(v);
        }
    }
}

// ===========================================================================
// Kernel 2: down projection, out[M,H] = t @ wd^T. Single CTA, BM=256, BN=256.
// Stage = t(32K) + wd(32K) = 64KB, 3 stages. TMEM 512: D m0 [0,256), m1 [256,512).
// ===========================================================================
__global__ __launch_bounds__(256)
void down_mma(const __grid_constant__ CUtensorMap mt,
              const __grid_constant__ CUtensorMap mw,
              const float* __restrict__ wd, float* __restrict__ out,
              int M, int H, int I)
{
    const int GX = gridDim.x;                    // H/256 = 16
    const int lin = blockIdx.y * GX + blockIdx.x;
    const int band = lin / (4 * GX);
    const int rr = lin - band * 4 * GX;
    const int bn = (rr >> 2) * 256;
    const int bm = (band * 4 + (rr & 3)) * 256;

#if TC_OK
    extern __shared__ __align__(1024) char smem[];
    const uint32_t sb = smem_u32(smem);
    constexpr uint32_t STAGE0 = 2048, SSZ = 65536;
    constexpr int NS = 3;
    const uint32_t FULL = sb + 16, DONE = sb + 80;

    const int tid = threadIdx.x;
    const int wid = tid >> 5;
    const int lane = tid & 31;

    if (wid == 0) tmem_alloc(sb, 512);
    if (tid == 0) {
#pragma unroll
        for (int s = 0; s < NS; ++s) { mbar_init(FULL + 8 * s, 1); mbar_init(DONE + 8 * s, 1); }
        FENCE_ASYNC_SHARED();
    }
    __syncthreads();
    const uint32_t tmem = *(volatile uint32_t*)smem;
    const int nchunks = I / 32;

    if (wid == 0) {
        int phf[NS] = {}, phd[NS] = {};
        const uint32_t e1 = elect_one();
        if (e1) {
#pragma unroll
            for (int s = 0; s < NS; ++s) {
                const uint32_t sa = sb + STAGE0 + (uint32_t)s * SSZ;
                mbar_expect_tx(FULL + 8 * s, 65536);
                tma2d(sa,         &mt, s * 32, bm, FULL + 8 * s);   // t  256 rows
                tma2d(sa + 32768, &mw, s * 32, bn, FULL + 8 * s);   // wd 256 rows
            }
        }
        int s = 0;
        for (int kt = 0; kt < nchunks; ++kt) {
            mbar_wait(FULL + 8 * s, phf[s]); phf[s] ^= 1;
            if (e1) {
                const uint32_t sa = sb + STAGE0 + (uint32_t)s * SSZ;
                const uint64_t t0 = sdesc(sa),         t1 = sdesc(sa + 16384);
                const uint64_t w0 = sdesc(sa + 32768), w1 = sdesc(sa + 49152);
#pragma unroll
                for (int st = 0; st < 4; ++st) {
                    const uint32_t en = (kt > 0 || st > 0) ? 1u : 0u;
                    const uint64_t o = (uint64_t)(st * 2);
                    mma_tf32_ss(tmem,       t0 + o, w0 + o, IDESC_TF32, en);
                    mma_tf32_ss(tmem + 128, t0 + o, w1 + o, IDESC_TF32, en);
                    mma_tf32_ss(tmem + 256, t1 + o, w0 + o, IDESC_TF32, en);
                    mma_tf32_ss(tmem + 384, t1 + o, w1 + o, IDESC_TF32, en);
                }
                mma_commit(DONE + 8 * s);
            }
            const int tgt = kt + NS;
            if (tgt < nchunks) {
                mbar_wait(DONE + 8 * s, phd[s]); phd[s] ^= 1;
                if (e1) {
                    const uint32_t sa = sb + STAGE0 + (uint32_t)s * SSZ;
                    mbar_expect_tx(FULL + 8 * s, 65536);
                    tma2d(sa,         &mt, tgt * 32, bm, FULL + 8 * s);
                    tma2d(sa + 32768, &mw, tgt * 32, bn, FULL + 8 * s);
                }
            }
            if (++s == NS) s = 0;
        }
#pragma unroll
        for (int q = 0; q < NS; ++q) mbar_wait(DONE + 8 * q, phd[q]);
    }
    __syncthreads();
    TCGEN05_FENCE_AFTER();

    {
        const int half = wid >> 2;
        const int sub = wid & 3;
        const int token = bm + half * 128 + sub * 32 + lane;
        const uint32_t db = tmem + half * 256;
#pragma unroll
        for (int cc = 0; cc < 8; ++cc) {
            uint32_t r[32];
            ldtm_x32(r, db + cc * 32);
            TCGEN05_WAIT_LD();
            const size_t base = (size_t)token * H + bn + cc * 32;
#pragma unroll
            for (int q = 0; q < 8; ++q) {
                float4 v4;
                ((float*)&v4)[0] = __uint_as_float(r[q * 4 + 0]);
                ((float*)&v4)[1] = __uint_as_float(r[q * 4 + 1]);
                ((float*)&v4)[2] = __uint_as_float(r[q * 4 + 2]);
                ((float*)&v4)[3] = __uint_as_float(r[q * 4 + 3]);
                *(float4*)(out + base + q * 4) = v4;
            }
        }
    }
    TCGEN05_FENCE_BEFORE();
    __syncthreads();
    if (wid == 0) tmem_dealloc(tmem, 512);

#else // ---------------- fallback: FFMA down (4 subtiles) ------------------
    extern __shared__ char smem_raw[];
    constexpr int BK = 16, TM = 8, TN = 8, AST = 132;
    float* AsS = (float*)smem_raw;
    float* BsS = AsS + 2 * BK * AST;
#define A_AT(s,k,r) AsS[((s) * BK + (k)) * AST + (r)]
#define B_AT(s,k,r) BsS[((s) * BK + (k)) * AST + (r)]
    const int tid = threadIdx.x;
    const int tx = tid & 15, ty = tid >> 4;
    const int row0 = ty * TM, col0 = tx * TN;
    const int lr = tid >> 2, lk = (tid & 3) * 4;
    const int ktiles = I / BK;
    for (int mh = 0; mh < 2; ++mh) {
        const int bmh = bm + mh * 128;
        for (int half = 0; half < 2; ++half) {
            const int bnh = bn + half * 128;
            const float* pa0 = g_t_r + (size_t)(bmh + lr)      * I + lk;
            const float* pa1 = g_t_r + (size_t)(bmh + lr + 64) * I + lk;
            const float* pb0 = wd    + (size_t)(bnh + lr)      * I + lk;
            const float* pb1 = wd    + (size_t)(bnh + lr + 64) * I + lk;
            float acc[TM][TN] = {};
            {
                float4 a0 = *(const float4*)pa0;
                float4 a1 = *(const float4*)pa1;
                float4 b0 = *(const float4*)pb0;
                float4 b1 = *(const float4*)pb1;
                float av0[4] = {a0.x, a0.y, a0.z, a0.w};
                float av1[4] = {a1.x, a1.y, a1.z, a1.w};
                float bv0[4] = {b0.x, b0.y, b0.z, b0.w};
                float bv1[4] = {b1.x, b1.y, b1.z, b1.w};
#pragma unroll
                for (int e = 0; e < 4; e++) {
                    A_AT(0, lk + e, lr)      = av0[e];
                    A_AT(0, lk + e, lr + 64) = av1[e];
                    B_AT(0, lk + e, lr)      = bv0[e];
                    B_AT(0, lk + e, lr + 64) = bv1[e];
                }
            }
            __syncthreads();
            for (int kt = 0; kt < ktiles; ++kt) {
                const int cur = kt & 1, nxt = cur ^ 1;
                float4 na0, na1, nb0, nb1;
                const bool more = (kt + 1 < ktiles);
                if (more) {
                    const int off = (kt + 1) * BK;
                    na0 = *(const float4*)(pa0 + off);
                    na1 = *(const float4*)(pa1 + off);
                    nb0 = *(const float4*)(pb0 + off);
                    nb1 = *(const float4*)(pb1 + off);
                }
#pragma unroll
                for (int k = 0; k < BK; k++) {
                    float af[TM], bf[TN];
#pragma unroll
                    for (int i = 0; i < TM; i++) af[i] = A_AT(cur, k, row0 + i);
#pragma unroll
                    for (int j = 0; j < TN; j++) bf[j] = B_AT(cur, k, col0 + j);
#pragma unroll
                    for (int i = 0; i < TM; i++)
#pragma unroll
                        for (int j = 0; j < TN; j++)
                            acc[i][j] = fmaf(af[i], bf[j], acc[i][j]);
                }
                if (more) {
                    float av0[4] = {na0.x, na0.y, na0.z, na0.w};
                    float av1[4] = {na1.x, na1.y, na1.z, na1.w};
                    float bv0[4] = {nb0.x, nb0.y, nb0.z, nb0.w};
                    float bv1[4] = {nb1.x, nb1.y, nb1.z, nb1.w};
#pragma unroll
                    for (int e = 0; e < 4; e++) {
                        A_AT(nxt, lk + e, lr)      = av0[e];
                        A_AT(nxt, lk + e, lr + 64) = av1[e];
                        B_AT(nxt, lk + e, lr)      = bv0[e];
                        B_AT(nxt, lk + e, lr + 64) = bv1[e];
                    }
                }
                __syncthreads();
            }
#pragma unroll
            for (int i = 0; i < TM; i++) {
                const size_t rbase = (size_t)(bmh + row0 + i) * H + bnh + col0;
#pragma unroll
                for (int j = 0; j < TN; j++) out[rbase + j] = acc[i][j];
            }
            __syncthreads();
        }
    }
#undef A_AT
#undef B_AT
#endif
}

// ---------------------------------------------------------------------------
// Launch: pre-round -> reset -> upgate(+flag) -> fix -> down
// ---------------------------------------------------------------------------
typedef CUresult (CUDAAPI *EncodeFn)(CUtensorMap*, CUtensorMapDataType, cuuint32_t, void*,
    const cuuint64_t*, const cuuint64_t*, const cuuint32_t*, const cuuint32_t*,
    CUtensorMapInterleave, CUtensorMapSwizzle, CUtensorMapL2promotion, CUtensorMapFloatOOBfill);

extern "C" void kernel_launch(void* const* d_in, const int* in_sizes, int n_in,
                              void* d_out, int out_size)
{
    const float* x   = (const float*)d_in[0];
    const float* wg  = (const float*)d_in[1];
    const float* wu  = (const float*)d_in[2];
    const float* wd  = (const float*)d_in[3];
    const float* avg = (const float*)d_in[4];
    float* out = (float*)d_out;

    const int I = in_sizes[4];            // 14336
    const int H = in_sizes[3] / I;        // 4096
    const int M = in_sizes[0] / H;        // 8192

    cudaFuncSetAttribute(upgate_mma, cudaFuncAttributeMaxDynamicSharedMemorySize, SMEM_GEMM);
    cudaFuncSetAttribute(down_mma,   cudaFuncAttributeMaxDynamicSharedMemorySize, SMEM_GEMM);

    float *xr, *wur, *wgr, *wdr, *tr;
    cudaGetSymbolAddress((void**)&xr,  g_x_r);
    cudaGetSymbolAddress((void**)&wur, g_wu_r);
    cudaGetSymbolAddress((void**)&wgr, g_wg_r);
    cudaGetSymbolAddress((void**)&wdr, g_wd_r);
    cudaGetSymbolAddress((void**)&tr,  g_t_r);

    static EncodeFn enc = nullptr;
    if (!enc) {
        void* fp = nullptr;
        cudaDriverEntryPointQueryResult qr;
        cudaGetDriverEntryPoint("cuTensorMapEncodeTiled", &fp, cudaEnableDefault, &qr);
        enc = (EncodeFn)fp;
    }
    CUtensorMap mx, mu, mg, mt, mw;
    auto mk = [&](CUtensorMap* m, void* ptr, unsigned long long inner,
                  unsigned long long rows, unsigned boxRows) {
        cuuint64_t dims[2]    = {inner, rows};
        cuuint64_t strides[1] = {inner * 4};
        cuuint32_t box[2]     = {32u, boxRows};
        cuuint32_t es[2]      = {1u, 1u};
        enc(m, CU_TENSOR_MAP_DATA_TYPE_FLOAT32, 2, ptr, dims, strides, box, es,
            CU_TENSOR_MAP_INTERLEAVE_NONE, CU_TENSOR_MAP_SWIZZLE_128B,
            CU_TENSOR_MAP_L2_PROMOTION_L2_128B, CU_TENSOR_MAP_FLOAT_OOB_FILL_NONE);
    };
    mk(&mx, xr,  (unsigned long long)H, (unsigned long long)M, 256u);
    mk(&mu, wur, (unsigned long long)H, (unsigned long long)I, 128u);
    mk(&mg, wgr, (unsigned long long)H, (unsigned long long)I, 128u);
    mk(&mt, tr,  (unsigned long long)I, (unsigned long long)M, 256u);
    mk(&mw, wdr, (unsigned long long)I, (unsigned long long)H, 256u);

    round_tf32_kernel<<<2048, 256>>>(xr,  x,  (long long)M * H);
    round_tf32_kernel<<<2048, 256>>>(wur, wu, (long long)I * H);
    round_tf32_kernel<<<2048, 256>>>(wgr, wg, (long long)I * H);
    round_tf32_kernel<<<2048, 256>>>(wdr, wd, (long long)H * I);
    reset_fix_cnt<<<1, 32>>>();

    dim3 g1(I / 128, M / 256);            // 112 x 32
    upgate_mma<<<g1, 256, SMEM_GEMM>>>(mx, mu, mg, x, wg, wu, avg, M, H, I);

    fix_mask_kernel<<<2048, 256>>>(x, wg, wu, avg, H, I);

    dim3 g2(H / 256, M / 256);            // 16 x 32
    down_mma<<<g2, 256, SMEM_GEMM>>>(mt, mw, wd, out, M, H, I);
}